// round 17
// baseline (speedup 1.0000x reference)
#include <cuda_runtime.h>
#include <cuda_fp16.h>
#include <stdint.h>

#define TH 256
#define TM 64
#define HID 512
#define NIN 16
#define NOUT 136
#define HS 520              // H row stride (fp16): conflict-free for ldmatrix
#define XSTR 24             // X row stride (fp16)
#define NETS 137

#define XS_OFF  0                        // 64*16*4 = 4096
#define XH_OFF  4096                     // 64*24*2 = 3072
#define HH_OFF  (XH_OFF + 3072)          // 7168
#define SMEM_BYTES (HH_OFF + 66560)      // 73728
#define NET_OFF HH_OFF                   // netS overlays Hh (free after L2 MMAs)

// pair-packed fp16 weight fragments:
// [ks][ngpair][lane] -> {ngA.b0, ngA.b1, ngB.b0, ngB.b1}
// +1 k-step padding: rotating prefetch reads (never uses) ks==32.
__device__ __align__(16) uint2 g_W0f[64 * 32];          // 16 KB (L0, unpaired)
__device__ __align__(16) uint4 g_W1f[33 * 32 * 32];     // 528 KB
__device__ __align__(16) uint4 g_W2f[33 * 12 * 32];     // 198 KB (N padded to 192)

__device__ __forceinline__ uint32_t pack_h2(float a, float b)
{
    __half2 p = __floats2half2_rn(a, b);
    return *(uint32_t*)&p;
}

__global__ void prep_weights(const float* __restrict__ W0,
                             const float* __restrict__ W1,
                             const float* __restrict__ W2)
{
    int idx = blockIdx.x * blockDim.x + threadIdx.x;
    const int T0 = 64 * 32;
    const int T1 = 32 * 32 * 32;    // (ks, ngpair, lane)
    const int T2 = 32 * 12 * 32;
    if (idx < T0) {
        int lane = idx & 31, ng = idx >> 5;
        int g = lane >> 2, t = lane & 3;
        int n = ng * 8 + g;
        int k0 = 2 * t;
        uint2 o;
        o.x = pack_h2(W0[(k0    )*HID + n], W0[(k0 + 1)*HID + n]);
        o.y = pack_h2(W0[(k0 + 8)*HID + n], W0[(k0 + 9)*HID + n]);
        g_W0f[idx] = o;
    } else if (idx < T0 + T1) {
        int i = idx - T0;
        int lane = i & 31, ngp = (i >> 5) & 31, ks = i >> 10;
        int g = lane >> 2, t = lane & 3;
        int n0 = (ngp * 2) * 8 + g;
        int n1 = n0 + 8;
        int k0 = ks * 16 + 2 * t;
        uint4 o;
        o.x = pack_h2(W1[(k0    )*HID + n0], W1[(k0 + 1)*HID + n0]);
        o.y = pack_h2(W1[(k0 + 8)*HID + n0], W1[(k0 + 9)*HID + n0]);
        o.z = pack_h2(W1[(k0    )*HID + n1], W1[(k0 + 1)*HID + n1]);
        o.w = pack_h2(W1[(k0 + 8)*HID + n1], W1[(k0 + 9)*HID + n1]);
        g_W1f[ks * (32*32) + ngp * 32 + lane] = o;
    } else if (idx < T0 + T1 + T2) {
        int j = idx - T0 - T1;
        int lane = j & 31, ngp = (j >> 5) % 12, ks = j / (12 * 32);
        int g = lane >> 2, t = lane & 3;
        int wn = ngp / 3, jj = ngp % 3;
        int nt0 = 2 * jj, nt1 = 2 * jj + 1;
        int n0 = wn * 40 + nt0 * 8 + g;
        int n1 = (nt1 < 5) ? (wn * 40 + nt1 * 8 + g) : NOUT;
        int k0 = ks * 16 + 2 * t;
        float a00 = (n0 < NOUT) ? W2[(k0    )*NOUT + n0] : 0.0f;
        float a01 = (n0 < NOUT) ? W2[(k0 + 1)*NOUT + n0] : 0.0f;
        float a10 = (n0 < NOUT) ? W2[(k0 + 8)*NOUT + n0] : 0.0f;
        float a11 = (n0 < NOUT) ? W2[(k0 + 9)*NOUT + n0] : 0.0f;
        float c00 = (n1 < NOUT) ? W2[(k0    )*NOUT + n1] : 0.0f;
        float c01 = (n1 < NOUT) ? W2[(k0 + 1)*NOUT + n1] : 0.0f;
        float c10 = (n1 < NOUT) ? W2[(k0 + 8)*NOUT + n1] : 0.0f;
        float c11 = (n1 < NOUT) ? W2[(k0 + 9)*NOUT + n1] : 0.0f;
        uint4 o;
        o.x = pack_h2(a00, a01);
        o.y = pack_h2(a10, a11);
        o.z = pack_h2(c00, c01);
        o.w = pack_h2(c10, c11);
        g_W2f[ks * (12*32) + ngp * 32 + lane] = o;
    }
}

__device__ __forceinline__ void mma16816h(float* d, const uint32_t* a,
                                          uint32_t b0, uint32_t b1)
{
    asm volatile(
        "mma.sync.aligned.m16n8k16.row.col.f32.f16.f16.f32 "
        "{%0,%1,%2,%3}, {%4,%5,%6,%7}, {%8,%9}, {%0,%1,%2,%3};\n"
        : "+f"(d[0]), "+f"(d[1]), "+f"(d[2]), "+f"(d[3])
        : "r"(a[0]), "r"(a[1]), "r"(a[2]), "r"(a[3]),
          "r"(b0), "r"(b1));
}

__device__ __forceinline__ void ldsm4(uint32_t* r, uint32_t saddr)
{
    asm volatile("ldmatrix.sync.aligned.m8n8.x4.shared.b16 {%0,%1,%2,%3}, [%4];\n"
                 : "=r"(r[0]), "=r"(r[1]), "=r"(r[2]), "=r"(r[3])
                 : "r"(saddr));
}

__device__ __forceinline__ float ftanh(float x)
{
    float y;
    asm("tanh.approx.f32 %0, %1;" : "=f"(y) : "f"(x));
    return y;
}

__global__ __launch_bounds__(TH, 1)
void ptpd_mma_kernel(const float* __restrict__ pts,
                     const float* __restrict__ b0,
                     const float* __restrict__ b1, const float* __restrict__ b2,
                     float* __restrict__ out)
{
    extern __shared__ char sm[];
    float*  Xs  = (float*)(sm + XS_OFF);
    __half* Xh  = (__half*)(sm + XH_OFF);
    __half* Hh  = (__half*)(sm + HH_OFF);
    float*  netS = (float*)(sm + NET_OFF);   // overlays Hh after L2 MMAs

    const uint32_t smb = (uint32_t)__cvta_generic_to_shared(sm);
    const uint32_t xhS = smb + XH_OFF;
    const uint32_t hhS = smb + HH_OFF;

    const int tid  = threadIdx.x;
    const int lane = tid & 31;
    const int wid  = tid >> 5;
    const int g    = lane >> 2;
    const int t    = lane & 3;
    const long row0 = (long)blockIdx.x * TM;

    const int arow  = lane & 15;
    const int acol8 = (lane >> 4) << 3;

    // ---------------- X tile: fp32 + fp16 copy ----------------
    for (int i = tid; i < TM*NIN; i += TH) {
        float x = pts[row0*NIN + i];
        Xs[i] = x;
        int r = i >> 4, c = i & 15;
        Xh[r*XSTR + c] = __float2half_rn(x);
    }
    __syncthreads();

    // ---------------- layer 0 via MMA (K=16, single-term fp16) ----------------
    {
        float acc0[4][8][4];
        #pragma unroll
        for (int nt = 0; nt < 8; nt++) {
            int col = wid*64 + nt*8 + 2*t;
            float bv0 = b0[col], bv1 = b0[col + 1];
            #pragma unroll
            for (int mt = 0; mt < 4; mt++) {
                acc0[mt][nt][0] = bv0; acc0[mt][nt][1] = bv1;
                acc0[mt][nt][2] = bv0; acc0[mt][nt][3] = bv1;
            }
        }
        uint32_t xhf[4][4];
        #pragma unroll
        for (int mt = 0; mt < 4; mt++) {
            int ro = (mt*16 + arow)*XSTR + acol8;
            ldsm4(xhf[mt], xhS + ro*2);
        }
        const uint2* __restrict__ wp0 = g_W0f + (wid*8)*32 + lane;
        uint2 bv[8];
        #pragma unroll
        for (int nt = 0; nt < 8; nt++)
            bv[nt] = wp0[nt*32];
        #pragma unroll
        for (int nt = 0; nt < 8; nt++)
            #pragma unroll
            for (int mt = 0; mt < 4; mt++)
                mma16816h(acc0[mt][nt], xhf[mt], bv[nt].x, bv[nt].y);

        // tanh -> H0 (fp16)
        #pragma unroll
        for (int mt = 0; mt < 4; mt++)
            #pragma unroll
            for (int nt = 0; nt < 8; nt++) {
                int r   = mt*16 + g;
                int col = wid*64 + nt*8 + 2*t;
                *(__half2*)(Hh + r*HS + col) =
                    __floats2half2_rn(ftanh(acc0[mt][nt][0]), ftanh(acc0[mt][nt][1]));
                *(__half2*)(Hh + (r + 8)*HS + col) =
                    __floats2half2_rn(ftanh(acc0[mt][nt][2]), ftanh(acc0[mt][nt][3]));
            }
    }
    __syncthreads();

    // ====== layer 1: single-term fp16, pair-packed B, rotating prefetch ======
    {
        float acc1[4][8][4];
        #pragma unroll
        for (int nt = 0; nt < 8; nt++) {
            int col = wid*64 + nt*8 + 2*t;
            float bv0 = b1[col], bv1 = b1[col + 1];
            #pragma unroll
            for (int mt = 0; mt < 4; mt++) {
                acc1[mt][nt][0] = bv0; acc1[mt][nt][1] = bv1;
                acc1[mt][nt][2] = bv0; acc1[mt][nt][3] = bv1;
            }
        }

        const uint4* __restrict__ wp = g_W1f + (wid*4)*32 + lane;
        uint32_t a0 = hhS + (uint32_t)(arow*HS + acol8)*2;

        // peel: ks=0 fragments (4 x LDG.128)
        uint4 bv[4];
        #pragma unroll
        for (int j = 0; j < 4; j++)
            bv[j] = wp[j*32];
        wp += 32*32;

        for (int ks = 0; ks < 32; ks++) {
            uint32_t ah[4][4];
            #pragma unroll
            for (int mt = 0; mt < 4; mt++)
                ldsm4(ah[mt], a0 + (uint32_t)(mt*16*HS*2));
            a0 += 32;

            // use pair j (n-tiles 2j, 2j+1), then reload for ks+1
            #pragma unroll
            for (int j = 0; j < 4; j++) {
                #pragma unroll
                for (int mt = 0; mt < 4; mt++) {
                    mma16816h(acc1[mt][2*j],     ah[mt], bv[j].x, bv[j].y);
                    mma16816h(acc1[mt][2*j + 1], ah[mt], bv[j].z, bv[j].w);
                }
                bv[j] = wp[j*32];
            }
            wp += 32*32;
        }

        __syncthreads();    // all warps done READING H0 before overwrite

        // tanh -> H1 (overwrites H0)
        #pragma unroll
        for (int mt = 0; mt < 4; mt++)
            #pragma unroll
            for (int nt = 0; nt < 8; nt++) {
                int r   = mt*16 + g;
                int col = wid*64 + nt*8 + 2*t;
                *(__half2*)(Hh + r*HS + col) =
                    __floats2half2_rn(ftanh(acc1[mt][nt][0]), ftanh(acc1[mt][nt][1]));
                *(__half2*)(Hh + (r + 8)*HS + col) =
                    __floats2half2_rn(ftanh(acc1[mt][nt][2]), ftanh(acc1[mt][nt][3]));
            }
    }
    __syncthreads();

    // ====== layer 2: single-term fp16, pair-packed B, rotating prefetch ======
    {
        const int wm = wid & 1;      // 32 rows each (2 m-tiles)
        const int wn = wid >> 1;     // 40 cols (5 n-tiles)
        float acc2[2][5][4];
        #pragma unroll
        for (int nt = 0; nt < 5; nt++) {
            int col = wn*40 + nt*8 + 2*t;
            float bv0 = (col     < NOUT) ? b2[col]     : 0.0f;
            float bv1 = (col + 1 < NOUT) ? b2[col + 1] : 0.0f;
            #pragma unroll
            for (int mt = 0; mt < 2; mt++) {
                acc2[mt][nt][0] = bv0; acc2[mt][nt][1] = bv1;
                acc2[mt][nt][2] = bv0; acc2[mt][nt][3] = bv1;
            }
        }

        const uint4* __restrict__ wp2 = g_W2f + (wn*3)*32 + lane;
        uint32_t a0 = hhS + (uint32_t)((wm*32 + arow)*HS + acol8)*2;

        uint4 bv[3];
        #pragma unroll
        for (int j = 0; j < 3; j++)
            bv[j] = wp2[j*32];
        wp2 += 12*32;

        for (int ks = 0; ks < 32; ks++) {
            uint32_t ah[2][4];
            ldsm4(ah[0], a0);
            ldsm4(ah[1], a0 + (uint32_t)(16*HS*2));
            a0 += 32;

            #pragma unroll
            for (int mt = 0; mt < 2; mt++) {
                mma16816h(acc2[mt][0], ah[mt], bv[0].x, bv[0].y);
                mma16816h(acc2[mt][1], ah[mt], bv[0].z, bv[0].w);
                mma16816h(acc2[mt][2], ah[mt], bv[1].x, bv[1].y);
                mma16816h(acc2[mt][3], ah[mt], bv[1].z, bv[1].w);
                mma16816h(acc2[mt][4], ah[mt], bv[2].x, bv[2].y);
            }
            bv[0] = wp2[0*32];
            bv[1] = wp2[1*32];
            bv[2] = wp2[2*32];
            wp2 += 12*32;
        }

        __syncthreads();   // all warps done READING H1 -> netS overlay safe

        // net -> smem (overlays Hh)
        #pragma unroll
        for (int mt = 0; mt < 2; mt++)
            #pragma unroll
            for (int nt = 0; nt < 5; nt++) {
                int r   = wm*32 + mt*16 + g;
                int col = wn*40 + nt*8 + 2*t;
                if (col + 1 < NOUT) {
                    netS[r*NETS + col]           = acc2[mt][nt][0];
                    netS[r*NETS + col + 1]       = acc2[mt][nt][1];
                    netS[(r + 8)*NETS + col]     = acc2[mt][nt][2];
                    netS[(r + 8)*NETS + col + 1] = acc2[mt][nt][3];
                }
            }
    }
    __syncthreads();

    // ---------------- quadratic form ----------------
    if (tid < TM) {
        const float* nn = netS + tid*NETS;
        const float* xv = Xs + tid*NIN;
        float x[NIN], sx = 0.0f;
        #pragma unroll
        for (int i = 0; i < NIN; i++) { x[i] = xv[i]; sx = fmaf(x[i], x[i], sx); }
        float y[NIN];
        #pragma unroll
        for (int j = 0; j < NIN; j++) y[j] = 0.0f;
        int tt = 0;
        #pragma unroll
        for (int i = 0; i < NIN; i++) {
            #pragma unroll
            for (int j = 0; j <= i; j++) {
                y[j] = fmaf(nn[tt], x[i], y[j]);
                tt++;
            }
        }
        float v = 0.0f;
        #pragma unroll
        for (int j = 0; j < NIN; j++) v = fmaf(y[j], y[j], v);
        out[row0 + tid] = v + 1e-6f * sx;
    }
}

extern "C" void kernel_launch(void* const* d_in, const int* in_sizes, int n_in,
                              void* d_out, int out_size)
{
    const float* pts = (const float*)d_in[0];
    const float* W0  = (const float*)d_in[1];
    const float* b0  = (const float*)d_in[2];
    const float* W1  = (const float*)d_in[3];
    const float* b1  = (const float*)d_in[4];
    const float* W2  = (const float*)d_in[5];
    const float* b2  = (const float*)d_in[6];
    float* out = (float*)d_out;

    const int B = in_sizes[0] / NIN;

    cudaFuncSetAttribute(ptpd_mma_kernel,
                         cudaFuncAttributeMaxDynamicSharedMemorySize, SMEM_BYTES);

    const int prep_threads = 64*32 + 32*32*32 + 32*12*32;
    prep_weights<<<(prep_threads + 255)/256, 256>>>(W0, W1, W2);

    ptpd_mma_kernel<<<B/TM, TH, SMEM_BYTES>>>(pts, b0, b1, b2, out);
}